// round 17
// baseline (speedup 1.0000x reference)
#include <cuda_runtime.h>
#include <cuda_fp16.h>
#include <stdint.h>

#define B 4
#define S 2048
#define H 8
#define E 64
#define BH (B*H)
#define FQ 72   // smem row stride (halves)

// ---------------------------------------------------------------------------
// Device scratch (allocation-free)
// ---------------------------------------------------------------------------
__device__ __half g_qh[(size_t)BH*S*E];   // fp16 of 0.125*Qproj [bh][s][e]
__device__ __half g_kh[(size_t)BH*S*E];   // fp16 of Kproj
__device__ __half g_vh[(size_t)BH*E*S];   // fp16 of Vproj, transposed [bh][e][s]

// ---------------------------------------------------------------------------
// MMA helpers
// ---------------------------------------------------------------------------
__device__ __forceinline__ uint32_t smem_to_u32(const void* p) {
    uint32_t a;
    asm("{ .reg .u64 t; cvta.to.shared.u64 t, %1; cvt.u32.u64 %0, t; }" : "=r"(a) : "l"(p));
    return a;
}
__device__ __forceinline__ uint32_t pack_h2(float a, float b) {
    return (uint32_t)__half_as_ushort(__float2half_rn(a)) |
           ((uint32_t)__half_as_ushort(__float2half_rn(b)) << 16);
}
#define LDSM_X4(R0, R1, R2, R3, ADDR) \
    asm volatile("ldmatrix.sync.aligned.m8n8.x4.shared.b16 {%0,%1,%2,%3}, [%4];" \
                 : "=r"(R0), "=r"(R1), "=r"(R2), "=r"(R3) : "r"(ADDR))
#define MMA16816(C, A0, A1, A2, A3, B0, B1) \
    asm volatile("mma.sync.aligned.m16n8k16.row.col.f32.f16.f16.f32 " \
                 "{%0,%1,%2,%3}, {%4,%5,%6,%7}, {%8,%9}, {%0,%1,%2,%3};" \
                 : "+f"((C)[0]), "+f"((C)[1]), "+f"((C)[2]), "+f"((C)[3]) \
                 : "r"(A0), "r"(A1), "r"(A2), "r"(A3), "r"(B0), "r"(B1))

// ---------------------------------------------------------------------------
// Threefry2x32 (JAX partitionable) — validated rounds 1-16
// ---------------------------------------------------------------------------
__device__ __forceinline__ uint32_t rotl32(uint32_t v, int s) { return __funnelshift_l(v, v, s); }
__device__ __forceinline__ uint32_t threefry_mask_bits(uint32_t idx) {
    const uint32_t ks0 = 0u, ks1 = 42u, ks2 = 0x1BD11BDAu ^ 42u;
    uint32_t x0 = ks0, x1 = idx + ks1;
#define TFR(r) { x0 += x1; x1 = rotl32(x1, r); x1 ^= x0; }
    TFR(13) TFR(15) TFR(26) TFR(6)
    x0 += ks1; x1 += ks2 + 1u;
    TFR(17) TFR(29) TFR(16) TFR(24)
    x0 += ks2; x1 += ks0 + 2u;
    TFR(13) TFR(15) TFR(26) TFR(6)
    x0 += ks0; x1 += ks1 + 3u;
    TFR(17) TFR(29) TFR(16) TFR(24)
    x0 += ks1; x1 += ks2 + 4u;
    TFR(13) TFR(15) TFR(26) TFR(6)
    x0 += ks2; x1 += ks0 + 5u;
#undef TFR
    return x0 ^ x1;
}
#define KEEP_THRESH (7549747u << 9)
#define C512 6.2383246250395075f   // ln(512): fp16 range guard, cancels in normalization

// ---------------------------------------------------------------------------
// Kernel 1: QKV projection via HMMA (round-13/14 version, ~41us)
// ---------------------------------------------------------------------------
#define PW 72
#define SYW 133

__global__ __launch_bounds__(256, 3) void proj_kernel(
    const float* __restrict__ qin, const float* __restrict__ kin, const float* __restrict__ vin,
    const float* __restrict__ Wq, const float* __restrict__ bq,
    const float* __restrict__ Wk, const float* __restrict__ bk,
    const float* __restrict__ Wv, const float* __restrict__ bv)
{
    extern __shared__ char dyn[];
    __half* sWH = (__half*)dyn;
    __half* sWL = sWH + 64 * PW;
    __half* sXH = sWL + 64 * PW;
    __half* sXL = sXH + 128 * PW;
    float*  sbv = (float*)(sXL + 128 * PW);
    uint32_t* sY = (uint32_t*)sXH;

    const int tid = threadIdx.x;
    const int s0 = blockIdx.x * 128;
    const int bh = blockIdx.y;
    const int m  = blockIdx.z;
    const int b = bh >> 3, h = bh & 7;

    const float* __restrict__ xin  = (m == 0) ? qin : ((m == 1) ? kin : vin);
    const float* __restrict__ W    = (m == 0) ? Wq  : ((m == 1) ? Wk  : Wv);
    const float* __restrict__ bias = (m == 0) ? bq  : ((m == 1) ? bk  : bv);

    for (int i = tid; i < 1024; i += 256) {
        int r = i >> 4, c4 = (i & 15) * 4;
        float4 wv = ((const float4*)W)[i];
        __half h0 = __float2half_rn(wv.x), h1 = __float2half_rn(wv.y);
        __half h2 = __float2half_rn(wv.z), h3 = __float2half_rn(wv.w);
        *(__half2*)(sWH + r * PW + c4)     = __halves2half2(h0, h1);
        *(__half2*)(sWH + r * PW + c4 + 2) = __halves2half2(h2, h3);
        *(__half2*)(sWL + r * PW + c4) = __halves2half2(
            __float2half_rn(wv.x - __half2float(h0)), __float2half_rn(wv.y - __half2float(h1)));
        *(__half2*)(sWL + r * PW + c4 + 2) = __halves2half2(
            __float2half_rn(wv.z - __half2float(h2)), __float2half_rn(wv.w - __half2float(h3)));
    }
    if (tid < 64) sbv[tid] = bias[tid];
    for (int i = tid; i < 2048; i += 256) {
        int r = i >> 4, c4 = (i & 15) * 4;
        float4 xv = ((const float4*)(xin + ((size_t)((b * S + s0 + r) * H + h)) * 64))[i & 15];
        __half h0 = __float2half_rn(xv.x), h1 = __float2half_rn(xv.y);
        __half h2 = __float2half_rn(xv.z), h3 = __float2half_rn(xv.w);
        *(__half2*)(sXH + r * PW + c4)     = __halves2half2(h0, h1);
        *(__half2*)(sXH + r * PW + c4 + 2) = __halves2half2(h2, h3);
        *(__half2*)(sXL + r * PW + c4) = __halves2half2(
            __float2half_rn(xv.x - __half2float(h0)), __float2half_rn(xv.y - __half2float(h1)));
        *(__half2*)(sXL + r * PW + c4 + 2) = __halves2half2(
            __float2half_rn(xv.z - __half2float(h2)), __float2half_rn(xv.w - __half2float(h3)));
    }
    __syncthreads();

    const int w = tid >> 5, lane = tid & 31;
    const int lr = lane & 7, lg = lane >> 3;
    const int er = lane >> 2, ec = (lane & 3) * 2;

    const int arow = w * 16 + lr + (lg & 1) * 8;
    const int acol = (lg >> 1) * 8;
    const int brow = lr + (lg >> 1) * 8;
    const int bcol = (lg & 1) * 8;

    const uint32_t uXH = smem_to_u32(sXH), uXL = smem_to_u32(sXL);
    const uint32_t uWH = smem_to_u32(sWH), uWL = smem_to_u32(sWL);

    float acc[8][4];
    #pragma unroll
    for (int j = 0; j < 8; j++)
        #pragma unroll
        for (int l = 0; l < 4; l++) acc[j][l] = 0.0f;

    #pragma unroll
    for (int ks = 0; ks < 4; ks++) {
        uint32_t aH[4], aL[4], bH[4][4], bL[4][4];
        LDSM_X4(aH[0], aH[1], aH[2], aH[3],
                uXH + (uint32_t)((arow * PW + acol + ks * 16) * 2));
        #pragma unroll
        for (int nbp = 0; nbp < 4; nbp++)
            LDSM_X4(bH[nbp][0], bH[nbp][1], bH[nbp][2], bH[nbp][3],
                    uWH + (uint32_t)(((brow + nbp * 16) * PW + bcol + ks * 16) * 2));
        #pragma unroll
        for (int nb = 0; nb < 8; nb++)
            MMA16816(acc[nb], aH[0], aH[1], aH[2], aH[3],
                     bH[nb >> 1][(nb & 1) * 2], bH[nb >> 1][(nb & 1) * 2 + 1]);
        #pragma unroll
        for (int nbp = 0; nbp < 4; nbp++)
            LDSM_X4(bL[nbp][0], bL[nbp][1], bL[nbp][2], bL[nbp][3],
                    uWL + (uint32_t)(((brow + nbp * 16) * PW + bcol + ks * 16) * 2));
        #pragma unroll
        for (int nb = 0; nb < 8; nb++)
            MMA16816(acc[nb], aH[0], aH[1], aH[2], aH[3],
                     bL[nb >> 1][(nb & 1) * 2], bL[nb >> 1][(nb & 1) * 2 + 1]);
        LDSM_X4(aL[0], aL[1], aL[2], aL[3],
                uXL + (uint32_t)((arow * PW + acol + ks * 16) * 2));
        #pragma unroll
        for (int nb = 0; nb < 8; nb++)
            MMA16816(acc[nb], aL[0], aL[1], aL[2], aL[3],
                     bH[nb >> 1][(nb & 1) * 2], bH[nb >> 1][(nb & 1) * 2 + 1]);
    }

    const float qs = (m == 0) ? 0.125f : 1.0f;
    const int row0 = w * 16 + er;

    if (m < 2) {
        __half* dh = ((m == 0) ? g_qh : g_kh) + ((size_t)bh * S + s0) * 64;
        #pragma unroll
        for (int nb = 0; nb < 8; nb++) {
            const int col = nb * 8 + ec;
            const float b0 = sbv[col], b1 = sbv[col + 1];
            #pragma unroll
            for (int rr = 0; rr < 2; rr++) {
                const int row = row0 + rr * 8;
                float v0 = (acc[nb][rr * 2 + 0] + b0) * qs;
                float v1 = (acc[nb][rr * 2 + 1] + b1) * qs;
                *(__half2*)(dh + (size_t)row * 64 + col) =
                    __halves2half2(__float2half_rn(v0), __float2half_rn(v1));
            }
        }
    } else {
        __syncthreads();
        #pragma unroll
        for (int nb = 0; nb < 8; nb++) {
            const int col = nb * 8 + ec;
            const float b0 = sbv[col], b1 = sbv[col + 1];
            #pragma unroll
            for (int rr = 0; rr < 2; rr++) {
                const int row = row0 + rr * 8;
                sY[col * SYW + row] =
                    (uint32_t)__half_as_ushort(__float2half_rn(acc[nb][rr*2+0] + b0));
                sY[(col + 1) * SYW + row] =
                    (uint32_t)__half_as_ushort(__float2half_rn(acc[nb][rr*2+1] + b1));
            }
        }
        __syncthreads();
        for (int i = tid; i < 1024; i += 256) {
            const int fr = i >> 4, c = i & 15;
            const int sb8 = c * 8;
            uint32_t y[8];
            #pragma unroll
            for (int j = 0; j < 8; j++) y[j] = sY[fr * SYW + sb8 + j];
            uint4 hv;
            hv.x = (y[0] & 0xffffu) | (y[1] << 16);
            hv.y = (y[2] & 0xffffu) | (y[3] << 16);
            hv.z = (y[4] & 0xffffu) | (y[5] << 16);
            hv.w = (y[6] & 0xffffu) | (y[7] << 16);
            *(uint4*)(g_vh + ((size_t)bh * 64 + fr) * S + s0 + sb8) = hv;
        }
    }
}
#define PROJ_SMEM ((2*64*PW + 2*128*PW) * 2 + 64 * 4)

// ---------------------------------------------------------------------------
// Kernel 2: fused flash attention (round-14 layout, 3 barriers/chunk):
// double-buffered K/V prefetch + redundant per-warp m/l (no tid<64 update).
// CTA: 64q x one bh; 8 warps = 2(q) x 4(k|e); warp softmax tile 32q x 16k.
// ---------------------------------------------------------------------------
__global__ __launch_bounds__(256, 3) void flash_kernel(float* __restrict__ out)
{
    extern __shared__ char smraw[];
    __half* sQ  = (__half*)smraw;             // [64][FQ]
    __half* sK0 = sQ + 64 * FQ;               // [64][FQ] x2 (double buffer)
    __half* sK1 = sK0 + 64 * FQ;
    __half* sV0 = sK1 + 64 * FQ;
    __half* sV1 = sV0 + 64 * FQ;
    __half* sAT = sV1 + 64 * FQ;              // [64][FQ]
    float*  sPm = (float*)(sAT + 64 * FQ);    // [4][64] max partials
    float*  sPs = sPm + 256;                  // [4][64] sum partials

    const int tid = threadIdx.x;
    const int q0 = blockIdx.x * 64, bh = blockIdx.y;

    const __half* qhp = g_qh + ((size_t)bh * S + q0) * 64;
    const __half* khp = g_kh + (size_t)bh * S * 64;
    const __half* vhp = g_vh + (size_t)bh * 64 * S;

    const int ldr = tid >> 3, ldc = (tid & 7) * 8;   // 256 threads cover 2 rows each

    // Q + chunk 0 staging
    for (int i = tid; i < 512; i += 256) {
        int r = i >> 3, cc = (i & 7) * 8;
        *(uint4*)(sQ + r * FQ + cc) = *(const uint4*)(qhp + r * 64 + cc);
        *(uint4*)(sK0 + r * FQ + cc) = *(const uint4*)(khp + (size_t)r * 64 + cc);
        *(uint4*)(sV0 + r * FQ + cc) = *(const uint4*)(vhp + (size_t)r * S + cc);
    }

    const int w = tid >> 5, lane = tid & 31;
    const int qrow0 = (w >> 2) * 32;
    const int kq = (w & 3) * 16;          // softmax k-quarter == PV e-quarter
    const int lr = lane & 7, lg = lane >> 3;
    const int er = lane >> 2, ec = (lane & 3) * 2;

    const int arow = qrow0 + lr + (lg & 1) * 8;
    const int acol = (lg >> 1) * 8;
    const int sbrow = kq + lr + (lg >> 1) * 8;   // K rows
    const int bcol = (lg & 1) * 8;
    const int pbrow = kq + lr + (lg >> 1) * 8;   // V e-rows (PV B)
    const int pacol = (lg >> 1) * 8;

    const uint32_t uQ = smem_to_u32(sQ), uAT = smem_to_u32(sAT);
    const uint32_t uK[2] = {smem_to_u32(sK0), smem_to_u32(sK1)};
    const uint32_t uV[2] = {smem_to_u32(sV0), smem_to_u32(sV1)};
    __half* sKb[2] = {sK0, sK1};
    __half* sVb[2] = {sV0, sV1};

    const int R0 = qrow0 + er, R1 = R0 + 8, R2 = R0 + 16, R3 = R0 + 24;
    const uint32_t ibase = (uint32_t)(bh * S + q0) * (uint32_t)S;

    float m[4] = {-1e30f, -1e30f, -1e30f, -1e30f};
    float l[4] = {0.0f, 0.0f, 0.0f, 0.0f};
    float oacc[2][2][4];
    #pragma unroll
    for (int i = 0; i < 2; i++)
        #pragma unroll
        for (int j = 0; j < 2; j++)
            #pragma unroll
            for (int k = 0; k < 4; k++) oacc[i][j][k] = 0.0f;

    for (int c = 0; c < 32; c++) {
        const int cur = c & 1, nxt = cur ^ 1;
        __syncthreads();   // B1: cur stores visible; prev PV reads of nxt buffers done

        // prefetch chunk c+1 (overlaps with score MMA below)
        if (c + 1 < 32) {
            #pragma unroll
            for (int rr = 0; rr < 2; rr++) {
                const int r = ldr + rr * 32;
                *(uint4*)(sKb[nxt] + r * FQ + ldc) =
                    *(const uint4*)(khp + (size_t)((c + 1) * 64 + r) * 64 + ldc);
                *(uint4*)(sVb[nxt] + r * FQ + ldc) =
                    *(const uint4*)(vhp + (size_t)r * S + (c + 1) * 64 + ldc);
            }
        }

        // ---- score MMA on cur buffer: warp strip 32q x 16k ----
        float acc[2][2][4];
        #pragma unroll
        for (int i = 0; i < 2; i++)
            #pragma unroll
            for (int j = 0; j < 2; j++)
                #pragma unroll
                for (int k = 0; k < 4; k++) acc[i][j][k] = 0.0f;
        #pragma unroll
        for (int ks = 0; ks < 4; ks++) {
            uint32_t a[2][4], bb[4];
            #pragma unroll
            for (int mt = 0; mt < 2; mt++)
                LDSM_X4(a[mt][0], a[mt][1], a[mt][2], a[mt][3],
                        uQ + (uint32_t)(((arow + mt * 16) * FQ + acol + ks * 16) * 2));
            LDSM_X4(bb[0], bb[1], bb[2], bb[3],
                    uK[cur] + (uint32_t)((sbrow * FQ + bcol + ks * 16) * 2));
            #pragma unroll
            for (int mt = 0; mt < 2; mt++)
                #pragma unroll
                for (int nb = 0; nb < 2; nb++)
                    MMA16816(acc[mt][nb], a[mt][0], a[mt][1], a[mt][2], a[mt][3],
                             bb[nb * 2], bb[nb * 2 + 1]);
        }

        // ---- per-quarter row max -> sPm ----
        #pragma unroll
        for (int mt = 0; mt < 2; mt++) {
            float m0 = fmaxf(fmaxf(acc[mt][0][0], acc[mt][0][1]),
                             fmaxf(acc[mt][1][0], acc[mt][1][1]));
            float m1 = fmaxf(fmaxf(acc[mt][0][2], acc[mt][0][3]),
                             fmaxf(acc[mt][1][2], acc[mt][1][3]));
            m0 = fmaxf(m0, __shfl_xor_sync(0xffffffffu, m0, 1));
            m0 = fmaxf(m0, __shfl_xor_sync(0xffffffffu, m0, 2));
            m1 = fmaxf(m1, __shfl_xor_sync(0xffffffffu, m1, 1));
            m1 = fmaxf(m1, __shfl_xor_sync(0xffffffffu, m1, 2));
            if ((lane & 3) == 0) {
                sPm[(w & 3) * 64 + qrow0 + mt * 16 + er] = m0;
                sPm[(w & 3) * 64 + qrow0 + mt * 16 + er + 8] = m1;
            }
        }
        __syncthreads();   // S3

        // ---- redundant online update (identical across quarter warps) ----
        float resc[4], mr[4];
        const int Rr[4] = {R0, R1, R2, R3};
        #pragma unroll
        for (int rr = 0; rr < 4; rr++) {
            const int row = Rr[rr];
            float cm = fmaxf(fmaxf(sPm[row], sPm[64 + row]),
                             fmaxf(sPm[128 + row], sPm[192 + row]));
            float mn = fmaxf(m[rr], cm);
            resc[rr] = __expf(m[rr] - mn);
            m[rr] = mn;
            mr[rr] = mn;
        }
        #pragma unroll
        for (int nb = 0; nb < 2; nb++) {
            oacc[0][nb][0] *= resc[0]; oacc[0][nb][1] *= resc[0];
            oacc[0][nb][2] *= resc[1]; oacc[0][nb][3] *= resc[1];
            oacc[1][nb][0] *= resc[2]; oacc[1][nb][1] *= resc[2];
            oacc[1][nb][2] *= resc[3]; oacc[1][nb][3] *= resc[3];
        }

        // ---- exp + sums + threefry + fp16 -> sAT ----
        {
            float s0 = 0.0f, s1 = 0.0f, s2 = 0.0f, s3 = 0.0f;
            #pragma unroll
            for (int nb = 0; nb < 2; nb++) {
                acc[0][nb][0] = __expf(acc[0][nb][0] - mr[0] + C512);
                acc[0][nb][1] = __expf(acc[0][nb][1] - mr[0] + C512);
                acc[0][nb][2] = __expf(acc[0][nb][2] - mr[1] + C512);
                acc[0][nb][3] = __expf(acc[0][nb][3] - mr[1] + C512);
                acc[1][nb][0] = __expf(acc[1][nb][0] - mr[2] + C512);
                acc[1][nb][1] = __expf(acc[1][nb][1] - mr[2] + C512);
                acc[1][nb][2] = __expf(acc[1][nb][2] - mr[3] + C512);
                acc[1][nb][3] = __expf(acc[1][nb][3] - mr[3] + C512);
                s0 += acc[0][nb][0] + acc[0][nb][1];
                s1 += acc[0][nb][2] + acc[0][nb][3];
                s2 += acc[1][nb][0] + acc[1][nb][1];
                s3 += acc[1][nb][2] + acc[1][nb][3];
            }
            s0 += __shfl_xor_sync(0xffffffffu, s0, 1);
            s0 += __shfl_xor_sync(0xffffffffu, s0, 2);
            s1 += __shfl_xor_sync(0xffffffffu, s1, 1);
            s1 += __shfl_xor_sync(0xffffffffu, s1, 2);
            s2 += __shfl_xor_sync(0xffffffffu, s2, 1);
            s2 += __shfl_xor_sync(0xffffffffu, s2, 2);
            s3 += __shfl_xor_sync(0xffffffffu, s3, 1);
            s3 += __shfl_xor_sync(0xffffffffu, s3, 2);
            if ((lane & 3) == 0) {
                sPs[(w & 3) * 64 + R0] = s0;
                sPs[(w & 3) * 64 + R1] = s1;
                sPs[(w & 3) * 64 + R2] = s2;
                sPs[(w & 3) * 64 + R3] = s3;
            }

            const uint32_t kg0 = (uint32_t)(c * 64 + kq + ec);
            #pragma unroll
            for (int mt = 0; mt < 2; mt++)
                #pragma unroll
                for (int roff = 0; roff < 2; roff++) {
                    const int rloc = qrow0 + mt * 16 + roff * 8 + er;
                    const uint32_t idxb = ibase + (uint32_t)rloc * (uint32_t)S + kg0;
                    #pragma unroll
                    for (int nb = 0; nb < 2; nb++) {
                        const uint32_t i0 = idxb + nb * 8;
                        float va = acc[mt][nb][roff * 2 + 0];
                        float vb = acc[mt][nb][roff * 2 + 1];
                        if (threefry_mask_bits(i0)      >= KEEP_THRESH) va = 0.0f;
                        if (threefry_mask_bits(i0 + 1u) >= KEEP_THRESH) vb = 0.0f;
                        *(__half2*)(sAT + rloc * FQ + kq + nb * 8 + ec) =
                            __floats2half2_rn(va, vb);
                    }
                }
        }
        __syncthreads();   // S5: sAT + sPs visible

        // ---- redundant l update ----
        #pragma unroll
        for (int rr = 0; rr < 4; rr++) {
            const int row = Rr[rr];
            l[rr] = l[rr] * resc[rr] +
                    (sPs[row] + sPs[64 + row] + sPs[128 + row] + sPs[192 + row]);
        }

        // ---- PV MMA: oacc += attn(32q x 64k) @ V(64k x 16e per warp) ----
        #pragma unroll
        for (int ks = 0; ks < 4; ks++) {
            uint32_t a[2][4], bf[4];
            #pragma unroll
            for (int mt = 0; mt < 2; mt++)
                LDSM_X4(a[mt][0], a[mt][1], a[mt][2], a[mt][3],
                        uAT + (uint32_t)(((arow + mt * 16) * FQ + pacol + ks * 16) * 2));
            LDSM_X4(bf[0], bf[1], bf[2], bf[3],
                    uV[cur] + (uint32_t)((pbrow * FQ + bcol + ks * 16) * 2));
            #pragma unroll
            for (int mt = 0; mt < 2; mt++)
                #pragma unroll
                for (int nb = 0; nb < 2; nb++)
                    MMA16816(oacc[mt][nb], a[mt][0], a[mt][1], a[mt][2], a[mt][3],
                             bf[nb * 2], bf[nb * 2 + 1]);
        }
    }

    // epilogue: normalize from local l (identical across quarter warps)
    const float i0 = 1.0f / (0.9f * l[0]);
    const float i1 = 1.0f / (0.9f * l[1]);
    const float i2 = 1.0f / (0.9f * l[2]);
    const float i3 = 1.0f / (0.9f * l[3]);
    float* dst = out + ((size_t)bh * S + q0 + qrow0) * 64 + kq;  // e-quarter = kq
    #pragma unroll
    for (int nb = 0; nb < 2; nb++) {
        *(float2*)(dst + (size_t)(er) * 64 + nb * 8 + ec) =
            make_float2(oacc[0][nb][0] * i0, oacc[0][nb][1] * i0);
        *(float2*)(dst + (size_t)(er + 8) * 64 + nb * 8 + ec) =
            make_float2(oacc[0][nb][2] * i1, oacc[0][nb][3] * i1);
        *(float2*)(dst + (size_t)(16 + er) * 64 + nb * 8 + ec) =
            make_float2(oacc[1][nb][0] * i2, oacc[1][nb][1] * i2);
        *(float2*)(dst + (size_t)(16 + er + 8) * 64 + nb * 8 + ec) =
            make_float2(oacc[1][nb][2] * i3, oacc[1][nb][3] * i3);
    }
}
#define FL_SMEM (6 * 64 * FQ * 2 + 512 * 4)

// ---------------------------------------------------------------------------
extern "C" void kernel_launch(void* const* d_in, const int* in_sizes, int n_in,
                              void* d_out, int out_size) {
    (void)in_sizes; (void)n_in; (void)out_size;
    const float* query = (const float*)d_in[0];
    const float* key   = (const float*)d_in[1];
    const float* value = (const float*)d_in[2];
    const float* Wq    = (const float*)d_in[3];
    const float* bq    = (const float*)d_in[4];
    const float* Wk    = (const float*)d_in[5];
    const float* bk    = (const float*)d_in[6];
    const float* Wv    = (const float*)d_in[7];
    const float* bv    = (const float*)d_in[8];
    float* out = (float*)d_out;

    cudaFuncSetAttribute(proj_kernel,  cudaFuncAttributeMaxDynamicSharedMemorySize, PROJ_SMEM);
    cudaFuncSetAttribute(flash_kernel, cudaFuncAttributeMaxDynamicSharedMemorySize, FL_SMEM);

    dim3 pg(S / 128, BH, 3);
    proj_kernel<<<pg, 256, PROJ_SMEM>>>(query, key, value, Wq, bq, Wk, bk, Wv, bv);

    dim3 fg(S / 64, BH);
    flash_kernel<<<fg, 256, FL_SMEM>>>(out);
}